// round 4
// baseline (speedup 1.0000x reference)
#include <cuda_runtime.h>
#include <cstdint>

// ---------------------------------------------------------------------------
// Sinkhorn-Knopp, 65536 independent 32x32 fp32 matrices, 10 iterations.
//
// M after k normalizations == diag(u) * M0 * diag(v)  -> iterate only u, v:
//   d_i = sum_j M0[i][j] v_j ;  u_i <- u_i / (u_i d_i + eps)
//   c_j = sum_i M0[i][j] u_i ;  v_j <- v_j / (v_j c_j + eps)
//
// One warp per matrix, 8x4 lane grid: a = lane>>2 (rows 4a..4a+3),
// b = lane&3 (cols 8b..8b+7), g = a>>1. xor-slot register layout:
//   row slot r      <-> actual row  4a + (b^r)
//   col pair slot k <-> actual pair g^k  (cols 8b+2(g^k), +1; natural order)
// With this placement every cross-lane reduction and u/v allgather is a
// plain scalar shfl_xor butterfly: zero routing selects, zero indexed
// gathers, zero shared memory. 64-bit shuffles are avoided except where a
// full pair genuinely moves (v allgather / col reduce pairs).
// ---------------------------------------------------------------------------

#define FMA2(d, a, b, c) \
    asm("fma.rn.f32x2 %0, %1, %2, %3;" : "=l"(d) : "l"(a), "l"(b), "l"(c))
#define MUL2(d, a, b) \
    asm("mul.rn.f32x2 %0, %1, %2;" : "=l"(d) : "l"(a), "l"(b))
#define ADD2(d, a, b) \
    asm("add.rn.f32x2 %0, %1, %2;" : "=l"(d) : "l"(a), "l"(b))
#define PACK2(d, lo, hi) \
    asm("mov.b64 %0, {%1, %2};" : "=l"(d) : "f"(lo), "f"(hi))
#define UNPACK2(lo, hi, s) \
    asm("mov.b64 {%0, %1}, %2;" : "=f"(lo), "=f"(hi) : "l"(s))
#define RCPA(d, s) \
    asm("rcp.approx.f32 %0, %1;" : "=f"(d) : "f"(s))
#define EX2A(d, s) \
    asm("ex2.approx.f32 %0, %1;" : "=f"(d) : "f"(s))

using ull = unsigned long long;

static constexpr float    EPS   = 1e-8f;
static constexpr float    SCALE = 14.4269504088896340736f;  // 10 * log2(e)
static constexpr int      WPB   = 4;                         // warps per block
static constexpr unsigned FULL  = 0xFFFFFFFFu;

__device__ __forceinline__ ull shfl_xor64(ull x, int mask) {
    // 2 SASS SHFLs — used only where a genuine f32x2 pair moves.
    return __shfl_xor_sync(FULL, x, mask);
}

__global__ __launch_bounds__(WPB * 32, 6)
void sinkhorn_kernel(const float* __restrict__ H,
                     float* __restrict__ Out,
                     int nmat) {
    const int lane = threadIdx.x & 31;
    const int wid  = threadIdx.x >> 5;
    const int a    = lane >> 2;      // 0..7
    const int b    = lane & 3;       // 0..3
    const int g    = a >> 1;         // 0..3
    const int al   = a & 1;

    const int m = blockIdx.x * WPB + wid;
    if (m >= nmat) return;           // warp-uniform

    const float2* src = reinterpret_cast<const float2*>(H)  + (size_t)m * 512;
    float2*       dst = reinterpret_cast<float2*>(Out)      + (size_t)m * 512;

    ull SC2;  PACK2(SC2, SCALE, SCALE);
    ull ONE2; PACK2(ONE2, 1.0f, 1.0f);

    // ---- Load + exp + clamp straight into xor-slot layout (float2 LDGs) ---
    // M[r][k] = ( m0[4a+(b^r)][8b+2(g^k)], m0[4a+(b^r)][8b+2(g^k)+1] )
    ull M[4][4];
#pragma unroll
    for (int r = 0; r < 4; r++) {
        const int ro = (4 * a + (b ^ r)) * 16 + 4 * b;   // float2 index of row
#pragma unroll
        for (int k = 0; k < 4; k++) {
            float2 t = src[ro + (g ^ k)];
            ull p; PACK2(p, t.x, t.y);
            MUL2(p, p, SC2);
            float x, y; UNPACK2(x, y, p);
            EX2A(x, x); EX2A(y, y);
            x = fmaxf(x, EPS); y = fmaxf(y, EPS);
            PACK2(M[r][k], x, y);
        }
    }

    // State: u = u[4a+b] (scalar), v = v[8b+a] (scalar), V[k] = v-pair slot k
    float u = 1.0f, v = 1.0f;
    ull V[4];
    V[0] = ONE2; V[1] = ONE2; V[2] = ONE2; V[3] = ONE2;
    ull U2[4];

#pragma unroll 1
    for (int it = 0; it < 10; it++) {
        // ===== Row step: d over this lane's 8 cols, reduce over b-quad =====
        float D0, D1, D2, D3;
        {
            ull acc;
            MUL2(acc, M[0][0], V[0]); FMA2(acc, M[0][1], V[1], acc);
            FMA2(acc, M[0][2], V[2], acc); FMA2(acc, M[0][3], V[3], acc);
            float x, y; UNPACK2(x, y, acc); D0 = x + y;
            MUL2(acc, M[1][0], V[0]); FMA2(acc, M[1][1], V[1], acc);
            FMA2(acc, M[1][2], V[2], acc); FMA2(acc, M[1][3], V[3], acc);
            UNPACK2(x, y, acc); D1 = x + y;
            MUL2(acc, M[2][0], V[0]); FMA2(acc, M[2][1], V[1], acc);
            FMA2(acc, M[2][2], V[2], acc); FMA2(acc, M[2][3], V[3], acc);
            UNPACK2(x, y, acc); D2 = x + y;
            MUL2(acc, M[3][0], V[0]); FMA2(acc, M[3][1], V[1], acc);
            FMA2(acc, M[3][2], V[2], acc); FMA2(acc, M[3][3], V[3], acc);
            UNPACK2(x, y, acc); D3 = x + y;
        }
        // xor-slot reduce: slot r on lane b holds row 4a+(b^r)
        D0 += __shfl_xor_sync(FULL, D2, 2);
        D1 += __shfl_xor_sync(FULL, D3, 2);
        D0 += __shfl_xor_sync(FULL, D1, 1);      // full d[4a+b]
        // u <- u / (u*d + eps)
        { float t = fmaf(u, D0, EPS); float r0; RCPA(r0, t); u *= r0; }
        // allgather u into row slots: U2[r] = (u[4a+(b^r)], same)
        {
            float u1 = __shfl_xor_sync(FULL, u, 1);
            float u2 = __shfl_xor_sync(FULL, u, 2);
            float u3 = __shfl_xor_sync(FULL, u, 3);
            PACK2(U2[0], u,  u ); PACK2(U2[1], u1, u1);
            PACK2(U2[2], u2, u2); PACK2(U2[3], u3, u3);
        }

        // ===== Col step: pair partials over this lane's 4 rows =====
        ull C0, C1, C2, C3;
        MUL2(C0, M[0][0], U2[0]); FMA2(C0, M[1][0], U2[1], C0);
        FMA2(C0, M[2][0], U2[2], C0); FMA2(C0, M[3][0], U2[3], C0);
        MUL2(C1, M[0][1], U2[0]); FMA2(C1, M[1][1], U2[1], C1);
        FMA2(C1, M[2][1], U2[2], C1); FMA2(C1, M[3][1], U2[3], C1);
        MUL2(C2, M[0][2], U2[0]); FMA2(C2, M[1][2], U2[1], C2);
        FMA2(C2, M[2][2], U2[2], C2); FMA2(C2, M[3][2], U2[3], C2);
        MUL2(C3, M[0][3], U2[0]); FMA2(C3, M[1][3], U2[1], C3);
        FMA2(C3, M[2][3], U2[2], C3); FMA2(C3, M[3][3], U2[3], C3);
        // xor-slot reduce over the 8 a-lanes (pair payloads)
        {
            ull t;
            t = shfl_xor64(C2, 16); ADD2(C0, C0, t);
            t = shfl_xor64(C3, 16); ADD2(C1, C1, t);
            t = shfl_xor64(C1, 8);  ADD2(C0, C0, t);
            t = shfl_xor64(C0, 4);  ADD2(C0, C0, t);   // duo holds full pair g
        }
        float cx, cy; UNPACK2(cx, cy, C0);
        const float cs = al ? cy : cx;                 // col 8b + 2g + al = 8b+a
        // v <- v / (v*c + eps)
        { float t = fmaf(v, cs, EPS); float r0; RCPA(r0, t); v *= r0; }
        // allgather v into col pair slots: V[k] = pair (g^k), natural order
        {
            float t4 = __shfl_xor_sync(FULL, v, 4);    // duo partner
            const float lo = al ? t4 : v;
            const float hi = al ? v  : t4;
            PACK2(V[0], lo, hi);                       // own pair g
            V[1] = shfl_xor64(V[0], 8);
            V[2] = shfl_xor64(V[0], 16);
            V[3] = shfl_xor64(V[0], 24);
        }
    }

    // ---- Epilogue: out[i][j] = u_i * M0[i][j] * v_j (float2 stores) ----
#pragma unroll
    for (int r = 0; r < 4; r++) {
        const int ro = (4 * a + (b ^ r)) * 16 + 4 * b;
#pragma unroll
        for (int k = 0; k < 4; k++) {
            ull o;
            MUL2(o, M[r][k], V[k]);
            MUL2(o, o, U2[r]);
            float2 t; UNPACK2(t.x, t.y, o);
            dst[ro + (g ^ k)] = t;
        }
    }
}

extern "C" void kernel_launch(void* const* d_in, const int* in_sizes, int n_in,
                              void* d_out, int out_size) {
    const float* H   = (const float*)d_in[0];
    float*       out = (float*)d_out;
    const int nmat   = in_sizes[0] / 1024;          // 32*32 per matrix
    const int blocks = (nmat + WPB - 1) / WPB;
    sinkhorn_kernel<<<blocks, WPB * 32>>>(H, out, nmat);
}

// round 5
// speedup vs baseline: 1.5591x; 1.5591x over previous
#include <cuda_runtime.h>
#include <cstdint>

// ---------------------------------------------------------------------------
// Sinkhorn-Knopp, 65536 independent 32x32 fp32 matrices, 10 iterations.
//
// M after k normalizations == diag(u) * M0 * diag(v)  -> iterate only u, v:
//   d_i = sum_j M0[i][j] v_j ;  u_i <- u_i / (u_i d_i + eps)
//   c_j = sum_i M0[i][j] u_i ;  v_j <- v_j / (v_j c_j + eps)
//
// One warp per matrix, 8x4 lane grid: a = lane>>2 (rows 4a..4a+3),
// b = lane&3 (cols 8b..8b+7), g = a>>1. xor-slot REGISTER layout:
//   row slot r      <-> actual row  4a + (b^r)
//   col pair slot k <-> actual col pair g^k (cols 8b+2(g^k), +1, natural
//                       element order)
// so every cross-lane reduction and u/v allgather in the iteration is a
// plain shfl_xor butterfly — zero routing selects, zero indexed gathers,
// zero shared memory.
//
// Memory stays on R2's proven float4 pattern (L2 24%): the row xor is a pure
// address permutation; the column xor is realized by loading float4 index
// g1^T and doing a one-time g0-conditional pair swap in registers (16 SELs
// at load + 16 at store, outside the iteration loop). This avoids R4's
// float2 scatter that drove L2 to 81%.
// ---------------------------------------------------------------------------

#define FMA2(d, a, b, c) \
    asm("fma.rn.f32x2 %0, %1, %2, %3;" : "=l"(d) : "l"(a), "l"(b), "l"(c))
#define MUL2(d, a, b) \
    asm("mul.rn.f32x2 %0, %1, %2;" : "=l"(d) : "l"(a), "l"(b))
#define ADD2(d, a, b) \
    asm("add.rn.f32x2 %0, %1, %2;" : "=l"(d) : "l"(a), "l"(b))
#define PACK2(d, lo, hi) \
    asm("mov.b64 %0, {%1, %2};" : "=l"(d) : "f"(lo), "f"(hi))
#define UNPACK2(lo, hi, s) \
    asm("mov.b64 {%0, %1}, %2;" : "=f"(lo), "=f"(hi) : "l"(s))
#define RCPA(d, s) \
    asm("rcp.approx.f32 %0, %1;" : "=f"(d) : "f"(s))
#define EX2A(d, s) \
    asm("ex2.approx.f32 %0, %1;" : "=f"(d) : "f"(s))

using ull = unsigned long long;

static constexpr float    EPS   = 1e-8f;
static constexpr float    SCALE = 14.4269504088896340736f;  // 10 * log2(e)
static constexpr int      WPB   = 4;                        // warps per block
static constexpr unsigned FULL  = 0xFFFFFFFFu;

__device__ __forceinline__ ull shfl_xor64(ull x, int mask) {
    return __shfl_xor_sync(FULL, x, mask);   // 2 SASS SHFLs
}

__global__ __launch_bounds__(WPB * 32, 6)
void sinkhorn_kernel(const float* __restrict__ H,
                     float* __restrict__ Out,
                     int nmat) {
    const int lane = threadIdx.x & 31;
    const int wid  = threadIdx.x >> 5;
    const int a    = lane >> 2;      // 0..7 (rows 4a..4a+3)
    const int b    = lane & 3;       // 0..3 (cols 8b..8b+7)
    const int g    = a >> 1;         // 0..3 (col-pair base)
    const int al   = a & 1;          // element of own col pair
    const int g0   = g & 1;          // pair-swap bit
    const int g1   = g >> 1;         // float4-select bit

    const int m = blockIdx.x * WPB + wid;
    if (m >= nmat) return;           // warp-uniform

    const float4* src = reinterpret_cast<const float4*>(H)  + (size_t)m * 256;
    float4*       dst = reinterpret_cast<float4*>(Out)      + (size_t)m * 256;

    ull SC2;  PACK2(SC2, SCALE, SCALE);
    ull ONE2; PACK2(ONE2, 1.0f, 1.0f);

    // ---- Load (float4, R2 pattern) + exp + clamp into xor-slot registers --
    // M[r][k] = ( m0[4a+(b^r)][8b+2(g^k)], m0[4a+(b^r)][8b+2(g^k)+1] )
    ull M[4][4];
#pragma unroll
    for (int r = 0; r < 4; r++) {
        const int base = (4 * a + (b ^ r)) * 8 + 2 * b;   // float4 index
#pragma unroll
        for (int T = 0; T < 2; T++) {
            float4 q = src[base + (g1 ^ T)];
            ull p0, p1;
            PACK2(p0, q.x, q.y);
            PACK2(p1, q.z, q.w);
            MUL2(p0, p0, SC2);
            MUL2(p1, p1, SC2);
            float x0, y0, x1, y1;
            UNPACK2(x0, y0, p0); UNPACK2(x1, y1, p1);
            EX2A(x0, x0); EX2A(y0, y0); EX2A(x1, x1); EX2A(y1, y1);
            x0 = fmaxf(x0, EPS); y0 = fmaxf(y0, EPS);
            x1 = fmaxf(x1, EPS); y1 = fmaxf(y1, EPS);
            ull lo, hi;
            PACK2(lo, x0, y0);
            PACK2(hi, x1, y1);
            // float4 (g1^T) holds col pairs 2(g1^T), 2(g1^T)+1; their slots
            // are 2T + (g0 ^ e): swap halves when g0 == 1.
            M[r][2 * T]     = g0 ? hi : lo;
            M[r][2 * T + 1] = g0 ? lo : hi;
        }
    }

    // State: u = u[4a+b] (scalar), v = v[8b+a] (scalar)
    float u = 1.0f, v = 1.0f;
    ull V[4];                       // V[k] = v-pair for actual pair g^k
    V[0] = ONE2; V[1] = ONE2; V[2] = ONE2; V[3] = ONE2;
    ull U2[4];                      // U2[r] = (u[4a+(b^r)], same)

#pragma unroll 1
    for (int it = 0; it < 10; it++) {
        // ===== Row step =====
        float D0, D1, D2, D3;
        {
            ull acc;
            MUL2(acc, M[0][0], V[0]); FMA2(acc, M[0][1], V[1], acc);
            FMA2(acc, M[0][2], V[2], acc); FMA2(acc, M[0][3], V[3], acc);
            float x, y; UNPACK2(x, y, acc); D0 = x + y;
            MUL2(acc, M[1][0], V[0]); FMA2(acc, M[1][1], V[1], acc);
            FMA2(acc, M[1][2], V[2], acc); FMA2(acc, M[1][3], V[3], acc);
            UNPACK2(x, y, acc); D1 = x + y;
            MUL2(acc, M[2][0], V[0]); FMA2(acc, M[2][1], V[1], acc);
            FMA2(acc, M[2][2], V[2], acc); FMA2(acc, M[2][3], V[3], acc);
            UNPACK2(x, y, acc); D2 = x + y;
            MUL2(acc, M[3][0], V[0]); FMA2(acc, M[3][1], V[1], acc);
            FMA2(acc, M[3][2], V[2], acc); FMA2(acc, M[3][3], V[3], acc);
            UNPACK2(x, y, acc); D3 = x + y;
        }
        // xor-slot reduce over b-quad (slot r on lane b holds row 4a+(b^r))
        D0 += __shfl_xor_sync(FULL, D2, 2);
        D1 += __shfl_xor_sync(FULL, D3, 2);
        D0 += __shfl_xor_sync(FULL, D1, 1);      // full d[4a+b]
        { float t = fmaf(u, D0, EPS); float r0; RCPA(r0, t); u *= r0; }
        // u allgather into row slots
        {
            float u1 = __shfl_xor_sync(FULL, u, 1);
            float u2 = __shfl_xor_sync(FULL, u, 2);
            float u3 = __shfl_xor_sync(FULL, u, 3);
            PACK2(U2[0], u,  u ); PACK2(U2[1], u1, u1);
            PACK2(U2[2], u2, u2); PACK2(U2[3], u3, u3);
        }

        // ===== Col step =====
        ull C0, C1, C2, C3;
        MUL2(C0, M[0][0], U2[0]); FMA2(C0, M[1][0], U2[1], C0);
        FMA2(C0, M[2][0], U2[2], C0); FMA2(C0, M[3][0], U2[3], C0);
        MUL2(C1, M[0][1], U2[0]); FMA2(C1, M[1][1], U2[1], C1);
        FMA2(C1, M[2][1], U2[2], C1); FMA2(C1, M[3][1], U2[3], C1);
        MUL2(C2, M[0][2], U2[0]); FMA2(C2, M[1][2], U2[1], C2);
        FMA2(C2, M[2][2], U2[2], C2); FMA2(C2, M[3][2], U2[3], C2);
        MUL2(C3, M[0][3], U2[0]); FMA2(C3, M[1][3], U2[1], C3);
        FMA2(C3, M[2][3], U2[2], C3); FMA2(C3, M[3][3], U2[3], C3);
        // xor-slot reduce over the 8 a-lanes (pair payloads)
        {
            ull t;
            t = shfl_xor64(C2, 16); ADD2(C0, C0, t);
            t = shfl_xor64(C3, 16); ADD2(C1, C1, t);
            t = shfl_xor64(C1, 8);  ADD2(C0, C0, t);
            t = shfl_xor64(C0, 4);  ADD2(C0, C0, t);   // full pair g
        }
        float cx, cy; UNPACK2(cx, cy, C0);
        const float cs = al ? cy : cx;                 // c[8b+a]
        { float t = fmaf(v, cs, EPS); float r0; RCPA(r0, t); v *= r0; }
        // v allgather into col-pair slots
        {
            float t4 = __shfl_xor_sync(FULL, v, 4);    // duo partner, same g
            const float lo = al ? t4 : v;
            const float hi = al ? v  : t4;
            PACK2(V[0], lo, hi);                       // own pair g
            V[1] = shfl_xor64(V[0], 8);
            V[2] = shfl_xor64(V[0], 16);
            V[3] = shfl_xor64(V[0], 24);
        }
    }

    // ---- Epilogue: out[i][j] = u_i * M0[i][j] * v_j (float4 stores) ----
#pragma unroll
    for (int r = 0; r < 4; r++) {
        const int base = (4 * a + (b ^ r)) * 8 + 2 * b;
#pragma unroll
        for (int T = 0; T < 2; T++) {
            ull o0, o1;
            MUL2(o0, M[r][2 * T],     V[2 * T]);
            MUL2(o0, o0, U2[r]);
            MUL2(o1, M[r][2 * T + 1], V[2 * T + 1]);
            MUL2(o1, o1, U2[r]);
            const ull xy = g0 ? o1 : o0;     // undo slot pair-swap
            const ull zw = g0 ? o0 : o1;
            float4 t;
            UNPACK2(t.x, t.y, xy);
            UNPACK2(t.z, t.w, zw);
            dst[base + (g1 ^ T)] = t;
        }
    }
}

extern "C" void kernel_launch(void* const* d_in, const int* in_sizes, int n_in,
                              void* d_out, int out_size) {
    const float* H   = (const float*)d_in[0];
    float*       out = (float*)d_out;
    const int nmat   = in_sizes[0] / 1024;          // 32*32 per matrix
    const int blocks = (nmat + WPB - 1) / WPB;
    sinkhorn_kernel<<<blocks, WPB * 32>>>(H, out, nmat);
}

// round 6
// speedup vs baseline: 1.6159x; 1.0364x over previous
#include <cuda_runtime.h>
#include <cstdint>

// ---------------------------------------------------------------------------
// Sinkhorn-Knopp, 65536 independent 32x32 fp32 matrices, 10 iterations.
//
// M after k normalizations == diag(u) * M0 * diag(v)  -> iterate only u, v:
//   d_i = sum_j M0[i][j] v_j ;  u_i <- u_i / (u_i d_i + eps)
//   c_j = sum_i M0[i][j] u_i ;  v_j <- v_j / (v_j c_j + eps)
//
// One warp per matrix, 8x4 lane grid: a = lane>>2 (rows), b = lane&3 (cols),
// g = a>>1. xor-slot REGISTER layout (iteration is pure shfl_xor, SEL-free):
//   row slot r      <-> actual row       4a + (b^r)
//   col pair slot k <-> actual col pair  g^k  of group b (cols 8b+2(g^k),+1)
//
// Global memory I/O is PERFECTLY FLAT (512B contiguous per warp instruction,
// 4 cache lines/inst). The flat <-> xor-slot mapping goes through a one-time
// per-warp padded smem tile (stride 36 floats): flat STS.128 / LDS.128 and
// per-slot LDS.64 / STS.64 are all bank-conflict-free (bank ~ 2R+P mod 16 is
// a permutation within each half-warp). This fixes R4/R5's L2 blowup (the
// xor permutation previously leaked into LDG addressing: 32 lines/inst).
// ---------------------------------------------------------------------------

#define FMA2(d, a, b, c) \
    asm("fma.rn.f32x2 %0, %1, %2, %3;" : "=l"(d) : "l"(a), "l"(b), "l"(c))
#define MUL2(d, a, b) \
    asm("mul.rn.f32x2 %0, %1, %2;" : "=l"(d) : "l"(a), "l"(b))
#define ADD2(d, a, b) \
    asm("add.rn.f32x2 %0, %1, %2;" : "=l"(d) : "l"(a), "l"(b))
#define PACK2(d, lo, hi) \
    asm("mov.b64 %0, {%1, %2};" : "=l"(d) : "f"(lo), "f"(hi))
#define UNPACK2(lo, hi, s) \
    asm("mov.b64 {%0, %1}, %2;" : "=f"(lo), "=f"(hi) : "l"(s))
#define RCPA(d, s) \
    asm("rcp.approx.f32 %0, %1;" : "=f"(d) : "f"(s))
#define EX2A(d, s) \
    asm("ex2.approx.f32 %0, %1;" : "=f"(d) : "f"(s))

using ull = unsigned long long;

static constexpr float    EPS   = 1e-8f;
static constexpr float    SCALE = 14.4269504088896340736f;  // 10 * log2(e)
static constexpr int      WPB   = 4;                        // warps per block
static constexpr int      SROW  = 36;                       // smem row stride
static constexpr unsigned FULL  = 0xFFFFFFFFu;

__device__ __forceinline__ ull shfl_xor64(ull x, int mask) {
    return __shfl_xor_sync(FULL, x, mask);   // 2 SASS SHFLs
}

__global__ __launch_bounds__(WPB * 32, 8)
void sinkhorn_kernel(const float* __restrict__ H,
                     float* __restrict__ Out,
                     int nmat) {
    __shared__ __align__(16) float S[WPB][32 * SROW];

    const int lane = threadIdx.x & 31;
    const int wid  = threadIdx.x >> 5;
    const int a    = lane >> 2;      // 0..7 (rows 4a..4a+3)
    const int b    = lane & 3;       // 0..3 (cols 8b..8b+7)
    const int g    = a >> 1;         // 0..3 (own col-pair index in group)
    const int al   = a & 1;          // element within own col pair

    const int m = blockIdx.x * WPB + wid;
    if (m >= nmat) return;           // warp-uniform

    float* s = S[wid];
    const float4* src = reinterpret_cast<const float4*>(H)  + (size_t)m * 256;
    float4*       dst = reinterpret_cast<float4*>(Out)      + (size_t)m * 256;

    ull SC2;  PACK2(SC2, SCALE, SCALE);
    ull ONE2; PACK2(ONE2, 1.0f, 1.0f);

    // ---- Flat load (4 lines/inst), scale+exp+clamp, flat STS into tile ----
#pragma unroll
    for (int k = 0; k < 8; k++) {
        const int f = k * 32 + lane;            // float4 index in matrix
        float4 q = src[f];
        ull p0, p1;
        PACK2(p0, q.x, q.y);
        PACK2(p1, q.z, q.w);
        MUL2(p0, p0, SC2);
        MUL2(p1, p1, SC2);
        float x0, y0, x1, y1;
        UNPACK2(x0, y0, p0); UNPACK2(x1, y1, p1);
        EX2A(x0, x0); EX2A(y0, y0); EX2A(x1, x1); EX2A(y1, y1);
        q.x = fmaxf(x0, EPS); q.y = fmaxf(y0, EPS);
        q.z = fmaxf(x1, EPS); q.w = fmaxf(y1, EPS);
        const int row = f >> 3;                 // 8 float4 per row
        const int ch  = f & 7;
        *reinterpret_cast<float4*>(s + row * SROW + ch * 4) = q;
    }
    __syncwarp();

    // ---- Gather xor-slot registers via conflict-free LDS.64 ----
    // M[r][k] = pair ( m0[4a+(b^r)][8b+2(g^k)], +1 )
    ull M[4][4];
#pragma unroll
    for (int r = 0; r < 4; r++) {
        const int R = 4 * a + (b ^ r);
#pragma unroll
        for (int k = 0; k < 4; k++) {
            const int P = 4 * b + (g ^ k);       // global col-pair index
            M[r][k] = *reinterpret_cast<const ull*>(s + R * SROW + 2 * P);
        }
    }

    // State: u = u[4a+b] (scalar), v = v[8b+a] (scalar)
    float u = 1.0f, v = 1.0f;
    ull V[4];                       // V[k] = v-pair for pair g^k of group b
    V[0] = ONE2; V[1] = ONE2; V[2] = ONE2; V[3] = ONE2;
    ull U2[4];                      // U2[r] = (u[4a+(b^r)], same)

#pragma unroll 1
    for (int it = 0; it < 10; it++) {
        // ===== Row step =====
        float D0, D1, D2, D3;
        {
            ull acc;
            MUL2(acc, M[0][0], V[0]); FMA2(acc, M[0][1], V[1], acc);
            FMA2(acc, M[0][2], V[2], acc); FMA2(acc, M[0][3], V[3], acc);
            float x, y; UNPACK2(x, y, acc); D0 = x + y;
            MUL2(acc, M[1][0], V[0]); FMA2(acc, M[1][1], V[1], acc);
            FMA2(acc, M[1][2], V[2], acc); FMA2(acc, M[1][3], V[3], acc);
            UNPACK2(x, y, acc); D1 = x + y;
            MUL2(acc, M[2][0], V[0]); FMA2(acc, M[2][1], V[1], acc);
            FMA2(acc, M[2][2], V[2], acc); FMA2(acc, M[2][3], V[3], acc);
            UNPACK2(x, y, acc); D2 = x + y;
            MUL2(acc, M[3][0], V[0]); FMA2(acc, M[3][1], V[1], acc);
            FMA2(acc, M[3][2], V[2], acc); FMA2(acc, M[3][3], V[3], acc);
            UNPACK2(x, y, acc); D3 = x + y;
        }
        // xor-slot reduce over b-quad (slot r on lane b holds row 4a+(b^r))
        D0 += __shfl_xor_sync(FULL, D2, 2);
        D1 += __shfl_xor_sync(FULL, D3, 2);
        D0 += __shfl_xor_sync(FULL, D1, 1);      // full d[4a+b]
        { float t = fmaf(u, D0, EPS); float r0; RCPA(r0, t); u *= r0; }
        // u allgather into row slots
        {
            float u1 = __shfl_xor_sync(FULL, u, 1);
            float u2 = __shfl_xor_sync(FULL, u, 2);
            float u3 = __shfl_xor_sync(FULL, u, 3);
            PACK2(U2[0], u,  u ); PACK2(U2[1], u1, u1);
            PACK2(U2[2], u2, u2); PACK2(U2[3], u3, u3);
        }

        // ===== Col step =====
        ull C0, C1, C2, C3;
        MUL2(C0, M[0][0], U2[0]); FMA2(C0, M[1][0], U2[1], C0);
        FMA2(C0, M[2][0], U2[2], C0); FMA2(C0, M[3][0], U2[3], C0);
        MUL2(C1, M[0][1], U2[0]); FMA2(C1, M[1][1], U2[1], C1);
        FMA2(C1, M[2][1], U2[2], C1); FMA2(C1, M[3][1], U2[3], C1);
        MUL2(C2, M[0][2], U2[0]); FMA2(C2, M[1][2], U2[1], C2);
        FMA2(C2, M[2][2], U2[2], C2); FMA2(C2, M[3][2], U2[3], C2);
        MUL2(C3, M[0][3], U2[0]); FMA2(C3, M[1][3], U2[1], C3);
        FMA2(C3, M[2][3], U2[2], C3); FMA2(C3, M[3][3], U2[3], C3);
        // xor-slot reduce over the 8 a-lanes
        {
            ull t;
            t = shfl_xor64(C2, 16); ADD2(C0, C0, t);
            t = shfl_xor64(C3, 16); ADD2(C1, C1, t);
            t = shfl_xor64(C1, 8);  ADD2(C0, C0, t);
        }
        // final mask-4 stage as a single scalar exchange:
        float cx, cy; UNPACK2(cx, cy, C0);
        const float send = al ? cx : cy;         // element partner needs
        const float recv = __shfl_xor_sync(FULL, send, 4);
        const float mine = al ? cy : cx;
        const float cs   = mine + recv;          // c[8b+2g+al] = c[8b+a]
        { float t = fmaf(v, cs, EPS); float r0; RCPA(r0, t); v *= r0; }
        // v allgather into col-pair slots
        {
            float t4 = __shfl_xor_sync(FULL, v, 4);    // pair partner
            const float lo = al ? t4 : v;
            const float hi = al ? v  : t4;
            PACK2(V[0], lo, hi);                       // own pair g
            V[1] = shfl_xor64(V[0], 8);
            V[2] = shfl_xor64(V[0], 16);
            V[3] = shfl_xor64(V[0], 24);
        }
    }

    // ---- Epilogue: out[i][j] = u_i * M0[i][j] * v_j ----
    // STS.64 per slot (conflict-free), then flat LDS.128 + flat STG.128.
#pragma unroll
    for (int r = 0; r < 4; r++) {
        const int R = 4 * a + (b ^ r);
#pragma unroll
        for (int k = 0; k < 4; k++) {
            const int P = 4 * b + (g ^ k);
            ull o;
            MUL2(o, M[r][k], V[k]);
            MUL2(o, o, U2[r]);
            *reinterpret_cast<ull*>(s + R * SROW + 2 * P) = o;
        }
    }
    __syncwarp();
#pragma unroll
    for (int k = 0; k < 8; k++) {
        const int f   = k * 32 + lane;
        const int row = f >> 3;
        const int ch  = f & 7;
        dst[f] = *reinterpret_cast<const float4*>(s + row * SROW + ch * 4);
    }
}

extern "C" void kernel_launch(void* const* d_in, const int* in_sizes, int n_in,
                              void* d_out, int out_size) {
    const float* H   = (const float*)d_in[0];
    float*       out = (float*)d_out;
    const int nmat   = in_sizes[0] / 1024;          // 32*32 per matrix
    const int blocks = (nmat + WPB - 1) / WPB;
    sinkhorn_kernel<<<blocks, WPB * 32>>>(H, out, nmat);
}